// round 9
// baseline (speedup 1.0000x reference)
#include <cuda_runtime.h>
#include <cstdint>

#define Bdim 4
#define Hdim 32
#define Tdim 2048
#define Kdim 64
#define Vdim 64
#define CHUNK 16
#define NCHUNK (Tdim / CHUNK)
#define NTHREADS 512
#define CHUNK_BYTES (CHUNK * Kdim * 4)   // 4096 B per tensor per chunk

// ---- packed f32x2 helpers (sm_103a FFMA2 path, PTX-only) ----
__device__ __forceinline__ float2 fma2(float2 a, float2 b, float2 c) {
    float2 d;
    asm("fma.rn.f32x2 %0, %1, %2, %3;"
        : "=l"(reinterpret_cast<unsigned long long&>(d))
        : "l"(reinterpret_cast<unsigned long long&>(a)),
          "l"(reinterpret_cast<unsigned long long&>(b)),
          "l"(reinterpret_cast<unsigned long long&>(c)));
    return d;
}
__device__ __forceinline__ float2 mul2(float2 a, float2 b) {
    float2 d;
    asm("mul.rn.f32x2 %0, %1, %2;"
        : "=l"(reinterpret_cast<unsigned long long&>(d))
        : "l"(reinterpret_cast<unsigned long long&>(a)),
          "l"(reinterpret_cast<unsigned long long&>(b)));
    return d;
}
__device__ __forceinline__ float2 add2(float2 a, float2 b) {
    float2 d;
    asm("add.rn.f32x2 %0, %1, %2;"
        : "=l"(reinterpret_cast<unsigned long long&>(d))
        : "l"(reinterpret_cast<unsigned long long&>(a)),
          "l"(reinterpret_cast<unsigned long long&>(b)));
    return d;
}

__device__ __forceinline__ void cp16(uint32_t smem_dst, const void* gmem_src) {
    asm volatile("cp.async.cg.shared.global [%0], [%1], 16;"
                 :: "r"(smem_dst), "l"(gmem_src));
}

// Block = one (b,h). 512 threads: vcol = tid>>3 (0..63), ks = tid&7 (K split 8x8).
// State S[k][v]: each thread holds its 8-k slice of its v-column as 4 packed float2.
// Per step: o_v = sum_k q_k*S_kv + v_v*(sum_k q_k*u_k*k_k);  S = S*exp(w) + k*v.
__global__ __launch_bounds__(NTHREADS, 1)
void rwkv6_scan_kernel(const float* __restrict__ r,
                       const float* __restrict__ kin,
                       const float* __restrict__ vin,
                       const float* __restrict__ win,
                       const float* __restrict__ uin,
                       const float* __restrict__ h0,
                       float* __restrict__ o,
                       float* __restrict__ hT) {
    const int bh    = blockIdx.x;
    const int h     = bh % Hdim;
    const int tid   = threadIdx.x;
    const int vcol  = tid >> 3;          // 0..63 (4 per warp)
    const int ks    = tid & 7;           // 0..7  (8 per vcol, within warp)
    const int kbase = ks * 8;

    __shared__ float sq[2][CHUNK][Kdim];
    __shared__ float sk[2][CHUNK][Kdim];
    __shared__ float sw[2][CHUNK][Kdim];   // exp() applied in place per chunk
    __shared__ float sv[2][CHUNK][Vdim];
    __shared__ float squk[2][CHUNK];       // per-step  sum_k q*u*k
    __shared__ float su[Kdim];

    // state slice: pair j holds k = kbase+2j, kbase+2j+1
    float2 s2[4];
    {
        const size_t hb = (size_t)bh * Kdim * Vdim;
#pragma unroll
        for (int j = 0; j < 4; j++) {
            s2[j].x = h0[hb + (size_t)(kbase + 2 * j)     * Vdim + vcol];
            s2[j].y = h0[hb + (size_t)(kbase + 2 * j + 1) * Vdim + vcol];
        }
    }
    if (tid < Kdim) su[tid] = uin[h * Kdim + tid];

    const size_t base = (size_t)bh * Tdim * Kdim;   // also valid for v and o (K==V)

    const uint32_t sq_s = (uint32_t)__cvta_generic_to_shared(&sq[0][0][0]);
    const uint32_t sk_s = (uint32_t)__cvta_generic_to_shared(&sk[0][0][0]);
    const uint32_t sw_s = (uint32_t)__cvta_generic_to_shared(&sw[0][0][0]);
    const uint32_t sv_s = (uint32_t)__cvta_generic_to_shared(&sv[0][0][0]);

    // issue a chunk's 4 tensors as one cp.async group into buffer `buf`
    // (first 256 threads move 16B each: 256*16 = 4096 B per tensor)
    auto issue_chunk = [&](int c, int buf) {
        if (tid < 256) {
            const size_t off = base + (size_t)c * CHUNK * Kdim;
            const uint32_t bofs = buf * CHUNK_BYTES + tid * 16;
            cp16(sq_s + bofs, r   + off + tid * 4);
            cp16(sk_s + bofs, kin + off + tid * 4);
            cp16(sw_s + bofs, win + off + tid * 4);
            cp16(sv_s + bofs, vin + off + tid * 4);
        }
        asm volatile("cp.async.commit_group;");
    };

    issue_chunk(0, 0);
    issue_chunk(1, 1);

    for (int c = 0; c < NCHUNK; c++) {
        const int cur = c & 1;
        asm volatile("cp.async.wait_group 1;");
        __syncthreads();

        // ---- per-chunk preprocessing ----
        // exp(w) in place: 1024 values / 512 threads = one float2 each
        {
            float2* wf = (float2*)&sw[cur][0][0];
            float2 t = wf[tid];
            t.x = __expf(t.x); t.y = __expf(t.y);
            wf[tid] = t;
        }
        // quk[t] = sum_k q*u*k : 16 steps x 32 threads, 2 k's each
        {
            const int stp  = tid >> 5;           // 0..15
            const int part = tid & 31;           // 0..31
            const float2 qq = *(const float2*)&sq[cur][stp][part * 2];
            const float2 kk = *(const float2*)&sk[cur][stp][part * 2];
            const float2 uu = *(const float2*)&su[part * 2];
            float sum = fmaf(qq.x * kk.x, uu.x, qq.y * kk.y * uu.y);
            sum += __shfl_xor_sync(0xffffffffu, sum, 1);
            sum += __shfl_xor_sync(0xffffffffu, sum, 2);
            sum += __shfl_xor_sync(0xffffffffu, sum, 4);
            sum += __shfl_xor_sync(0xffffffffu, sum, 8);
            sum += __shfl_xor_sync(0xffffffffu, sum, 16);
            if (part == 0) squk[cur][stp] = sum;
        }
        __syncthreads();

        // ---- compute 16 steps, no barriers ----
        const size_t obase = base + (size_t)c * CHUNK * Vdim;
#pragma unroll 2
        for (int tt = 0; tt < CHUNK; tt++) {
            const float4* q4 = (const float4*)&sq[cur][tt][kbase];
            const float4* k4 = (const float4*)&sk[cur][tt][kbase];
            const float4* e4 = (const float4*)&sw[cur][tt][kbase];
            const float myv = sv[cur][tt][vcol];
            const float2 vv = make_float2(myv, myv);

            float2 a0 = make_float2(0.f, 0.f), a1 = a0;
#pragma unroll
            for (int jj = 0; jj < 2; jj++) {
                const float4 qa = q4[jj];
                const float4 ka = k4[jj];
                const float4 ea = e4[jj];
                const float2 kvlo = mul2(make_float2(ka.x, ka.y), vv);
                const float2 kvhi = mul2(make_float2(ka.z, ka.w), vv);
                float2& acc = (jj == 0) ? a0 : a1;
                acc = fma2(make_float2(qa.x, qa.y), s2[2 * jj], acc);
                s2[2 * jj]     = fma2(s2[2 * jj],     make_float2(ea.x, ea.y), kvlo);
                acc = fma2(make_float2(qa.z, qa.w), s2[2 * jj + 1], acc);
                s2[2 * jj + 1] = fma2(s2[2 * jj + 1], make_float2(ea.z, ea.w), kvhi);
            }
            const float2 asum = add2(a0, a1);
            float acc = asum.x + asum.y;
            // reduce across the 8 ks-lanes (adjacent lanes in warp)
            acc += __shfl_xor_sync(0xffffffffu, acc, 1);
            acc += __shfl_xor_sync(0xffffffffu, acc, 2);
            acc += __shfl_xor_sync(0xffffffffu, acc, 4);
            if (ks == 0)
                o[obase + (size_t)tt * Vdim + vcol] = fmaf(squk[cur][tt], myv, acc);
        }
        __syncthreads();   // all reads of `cur` done before refill

        if (c + 2 < NCHUNK)
            issue_chunk(c + 2, cur);
    }

    // final state: layout (B,H,K,V)
    {
        const size_t hb = (size_t)bh * Kdim * Vdim;
#pragma unroll
        for (int j = 0; j < 4; j++) {
            hT[hb + (size_t)(kbase + 2 * j)     * Vdim + vcol] = s2[j].x;
            hT[hb + (size_t)(kbase + 2 * j + 1) * Vdim + vcol] = s2[j].y;
        }
    }
}

extern "C" void kernel_launch(void* const* d_in, const int* in_sizes, int n_in,
                              void* d_out, int out_size) {
    const float* r  = (const float*)d_in[0];
    const float* k  = (const float*)d_in[1];
    const float* v  = (const float*)d_in[2];
    const float* w  = (const float*)d_in[3];
    const float* u  = (const float*)d_in[4];
    const float* h0 = (const float*)d_in[5];

    float* o  = (float*)d_out;
    float* hT = o + (size_t)Bdim * Hdim * Tdim * Vdim;

    rwkv6_scan_kernel<<<Bdim * Hdim, NTHREADS>>>(r, k, v, w, u, h0, o, hT);
}

// round 10
// speedup vs baseline: 1.0018x; 1.0018x over previous
#include <cuda_runtime.h>
#include <cstdint>

#define Bdim 4
#define Hdim 32
#define Tdim 2048
#define Kdim 64
#define Vdim 64
#define CHUNK 16
#define NCHUNK (Tdim / CHUNK)
#define NTHREADS 512
#define CHUNK_BYTES (CHUNK * Kdim * 4)   // 4096 B per tensor per chunk

// ---- packed f32x2 helpers (sm_103a FFMA2 path, PTX-only) ----
__device__ __forceinline__ float2 fma2(float2 a, float2 b, float2 c) {
    float2 d;
    asm("fma.rn.f32x2 %0, %1, %2, %3;"
        : "=l"(reinterpret_cast<unsigned long long&>(d))
        : "l"(reinterpret_cast<unsigned long long&>(a)),
          "l"(reinterpret_cast<unsigned long long&>(b)),
          "l"(reinterpret_cast<unsigned long long&>(c)));
    return d;
}
__device__ __forceinline__ float2 mul2(float2 a, float2 b) {
    float2 d;
    asm("mul.rn.f32x2 %0, %1, %2;"
        : "=l"(reinterpret_cast<unsigned long long&>(d))
        : "l"(reinterpret_cast<unsigned long long&>(a)),
          "l"(reinterpret_cast<unsigned long long&>(b)));
    return d;
}
__device__ __forceinline__ float2 add2(float2 a, float2 b) {
    float2 d;
    asm("add.rn.f32x2 %0, %1, %2;"
        : "=l"(reinterpret_cast<unsigned long long&>(d))
        : "l"(reinterpret_cast<unsigned long long&>(a)),
          "l"(reinterpret_cast<unsigned long long&>(b)));
    return d;
}

__device__ __forceinline__ void cp16(uint32_t smem_dst, const void* gmem_src) {
    asm volatile("cp.async.cg.shared.global [%0], [%1], 16;"
                 :: "r"(smem_dst), "l"(gmem_src));
}

// Block = one (b,h). 512 threads: vcol = tid>>3 (0..63), ks = tid&7 (K split 8x8).
// State S[k][v]: each thread holds its 8-k slice of its v-column as 4 packed float2.
// Per step: o_v = sum_k q_k*S_kv + v_v*(sum_k q_k*u_k*k_k);  S = S*exp(w) + k*v.
__global__ __launch_bounds__(NTHREADS, 1)
void rwkv6_scan_kernel(const float* __restrict__ r,
                       const float* __restrict__ kin,
                       const float* __restrict__ vin,
                       const float* __restrict__ win,
                       const float* __restrict__ uin,
                       const float* __restrict__ h0,
                       float* __restrict__ o,
                       float* __restrict__ hT) {
    const int bh    = blockIdx.x;
    const int h     = bh % Hdim;
    const int tid   = threadIdx.x;
    const int vcol  = tid >> 3;          // 0..63 (4 per warp)
    const int ks    = tid & 7;           // 0..7  (8 per vcol, within warp)
    const int kbase = ks * 8;

    __shared__ float sq[2][CHUNK][Kdim];
    __shared__ float sk[2][CHUNK][Kdim];
    __shared__ float sw[2][CHUNK][Kdim];   // exp() applied in place per chunk
    __shared__ float sv[2][CHUNK][Vdim];
    __shared__ float squk[2][CHUNK];       // per-step  sum_k q*u*k
    __shared__ float su[Kdim];

    // state slice: pair j holds k = kbase+2j, kbase+2j+1
    float2 s2[4];
    {
        const size_t hb = (size_t)bh * Kdim * Vdim;
#pragma unroll
        for (int j = 0; j < 4; j++) {
            s2[j].x = h0[hb + (size_t)(kbase + 2 * j)     * Vdim + vcol];
            s2[j].y = h0[hb + (size_t)(kbase + 2 * j + 1) * Vdim + vcol];
        }
    }
    if (tid < Kdim) su[tid] = uin[h * Kdim + tid];

    const size_t base = (size_t)bh * Tdim * Kdim;   // also valid for v and o (K==V)

    const uint32_t sq_s = (uint32_t)__cvta_generic_to_shared(&sq[0][0][0]);
    const uint32_t sk_s = (uint32_t)__cvta_generic_to_shared(&sk[0][0][0]);
    const uint32_t sw_s = (uint32_t)__cvta_generic_to_shared(&sw[0][0][0]);
    const uint32_t sv_s = (uint32_t)__cvta_generic_to_shared(&sv[0][0][0]);

    // issue a chunk's 4 tensors as one cp.async group into buffer `buf`
    // (first 256 threads move 16B each: 256*16 = 4096 B per tensor)
    auto issue_chunk = [&](int c, int buf) {
        if (tid < 256) {
            const size_t off = base + (size_t)c * CHUNK * Kdim;
            const uint32_t bofs = buf * CHUNK_BYTES + tid * 16;
            cp16(sq_s + bofs, r   + off + tid * 4);
            cp16(sk_s + bofs, kin + off + tid * 4);
            cp16(sw_s + bofs, win + off + tid * 4);
            cp16(sv_s + bofs, vin + off + tid * 4);
        }
        asm volatile("cp.async.commit_group;");
    };

    issue_chunk(0, 0);
    issue_chunk(1, 1);

    for (int c = 0; c < NCHUNK; c++) {
        const int cur = c & 1;
        asm volatile("cp.async.wait_group 1;");
        __syncthreads();

        // ---- per-chunk preprocessing ----
        // exp(w) in place: 1024 values / 512 threads = one float2 each
        {
            float2* wf = (float2*)&sw[cur][0][0];
            float2 t = wf[tid];
            t.x = __expf(t.x); t.y = __expf(t.y);
            wf[tid] = t;
        }
        // quk[t] = sum_k q*u*k : 16 steps x 32 threads, 2 k's each
        {
            const int stp  = tid >> 5;           // 0..15
            const int part = tid & 31;           // 0..31
            const float2 qq = *(const float2*)&sq[cur][stp][part * 2];
            const float2 kk = *(const float2*)&sk[cur][stp][part * 2];
            const float2 uu = *(const float2*)&su[part * 2];
            float sum = fmaf(qq.x * kk.x, uu.x, qq.y * kk.y * uu.y);
            sum += __shfl_xor_sync(0xffffffffu, sum, 1);
            sum += __shfl_xor_sync(0xffffffffu, sum, 2);
            sum += __shfl_xor_sync(0xffffffffu, sum, 4);
            sum += __shfl_xor_sync(0xffffffffu, sum, 8);
            sum += __shfl_xor_sync(0xffffffffu, sum, 16);
            if (part == 0) squk[cur][stp] = sum;
        }
        __syncthreads();

        // ---- compute 16 steps, no barriers ----
        const size_t obase = base + (size_t)c * CHUNK * Vdim;
#pragma unroll 2
        for (int tt = 0; tt < CHUNK; tt++) {
            const float4* q4 = (const float4*)&sq[cur][tt][kbase];
            const float4* k4 = (const float4*)&sk[cur][tt][kbase];
            const float4* e4 = (const float4*)&sw[cur][tt][kbase];
            const float myv = sv[cur][tt][vcol];
            const float2 vv = make_float2(myv, myv);

            float2 a0 = make_float2(0.f, 0.f), a1 = a0;
#pragma unroll
            for (int jj = 0; jj < 2; jj++) {
                const float4 qa = q4[jj];
                const float4 ka = k4[jj];
                const float4 ea = e4[jj];
                const float2 kvlo = mul2(make_float2(ka.x, ka.y), vv);
                const float2 kvhi = mul2(make_float2(ka.z, ka.w), vv);
                float2& acc = (jj == 0) ? a0 : a1;
                acc = fma2(make_float2(qa.x, qa.y), s2[2 * jj], acc);
                s2[2 * jj]     = fma2(s2[2 * jj],     make_float2(ea.x, ea.y), kvlo);
                acc = fma2(make_float2(qa.z, qa.w), s2[2 * jj + 1], acc);
                s2[2 * jj + 1] = fma2(s2[2 * jj + 1], make_float2(ea.z, ea.w), kvhi);
            }
            const float2 asum = add2(a0, a1);
            float acc = asum.x + asum.y;
            // reduce across the 8 ks-lanes (adjacent lanes in warp)
            acc += __shfl_xor_sync(0xffffffffu, acc, 1);
            acc += __shfl_xor_sync(0xffffffffu, acc, 2);
            acc += __shfl_xor_sync(0xffffffffu, acc, 4);
            if (ks == 0)
                o[obase + (size_t)tt * Vdim + vcol] = fmaf(squk[cur][tt], myv, acc);
        }
        __syncthreads();   // all reads of `cur` done before refill

        if (c + 2 < NCHUNK)
            issue_chunk(c + 2, cur);
    }

    // final state: layout (B,H,K,V)
    {
        const size_t hb = (size_t)bh * Kdim * Vdim;
#pragma unroll
        for (int j = 0; j < 4; j++) {
            hT[hb + (size_t)(kbase + 2 * j)     * Vdim + vcol] = s2[j].x;
            hT[hb + (size_t)(kbase + 2 * j + 1) * Vdim + vcol] = s2[j].y;
        }
    }
}

extern "C" void kernel_launch(void* const* d_in, const int* in_sizes, int n_in,
                              void* d_out, int out_size) {
    const float* r  = (const float*)d_in[0];
    const float* k  = (const float*)d_in[1];
    const float* v  = (const float*)d_in[2];
    const float* w  = (const float*)d_in[3];
    const float* u  = (const float*)d_in[4];
    const float* h0 = (const float*)d_in[5];

    float* o  = (float*)d_out;
    float* hT = o + (size_t)Bdim * Hdim * Tdim * Vdim;

    rwkv6_scan_kernel<<<Bdim * Hdim, NTHREADS>>>(r, k, v, w, u, h0, o, hT);
}

// round 11
// speedup vs baseline: 3.5130x; 3.5068x over previous
#include <cuda_runtime.h>
#include <cstdint>

#define Bdim 4
#define Hdim 32
#define Tdim 2048
#define Kdim 64
#define Vdim 64
#define CHUNK 16
#define NCHUNK (Tdim / CHUNK)
#define NTHREADS 256
#define CHUNK_BYTES (CHUNK * Kdim * 4)   // 4096 B per tensor per chunk

// ---- packed f32x2 helpers (sm_103a FFMA2 path) ----
__device__ __forceinline__ float2 fma2(float2 a, float2 b, float2 c) {
    float2 d;
    asm("fma.rn.f32x2 %0, %1, %2, %3;"
        : "=l"(reinterpret_cast<unsigned long long&>(d))
        : "l"(reinterpret_cast<unsigned long long&>(a)),
          "l"(reinterpret_cast<unsigned long long&>(b)),
          "l"(reinterpret_cast<unsigned long long&>(c)));
    return d;
}
__device__ __forceinline__ float2 mul2(float2 a, float2 b) {
    float2 d;
    asm("mul.rn.f32x2 %0, %1, %2;"
        : "=l"(reinterpret_cast<unsigned long long&>(d))
        : "l"(reinterpret_cast<unsigned long long&>(a)),
          "l"(reinterpret_cast<unsigned long long&>(b)));
    return d;
}

__device__ __forceinline__ void cp16(uint32_t smem_dst, const void* gmem_src) {
    asm volatile("cp.async.cg.shared.global [%0], [%1], 16;"
                 :: "r"(smem_dst), "l"(gmem_src));
}

// Block = one (b,h). 256 threads: ks = tid&15 (K split 16x4), vg = tid>>4 (V split 16x4).
// Each thread owns a 4k x 4v state tile in registers (8 packed float2).
// Per step: o_v = sum_k q_k*S_kv + v_v*(sum_k q_k*u_k*k_k);  S = S*exp(w) + k*v.
__global__ __launch_bounds__(NTHREADS, 1)
void rwkv6_scan_kernel(const float* __restrict__ r,
                       const float* __restrict__ kin,
                       const float* __restrict__ vin,
                       const float* __restrict__ win,
                       const float* __restrict__ uin,
                       const float* __restrict__ h0,
                       float* __restrict__ o,
                       float* __restrict__ hT) {
    const int bh    = blockIdx.x;
    const int h     = bh % Hdim;
    const int tid   = threadIdx.x;
    const int ks    = tid & 15;          // k-group within warp halves
    const int vg    = tid >> 4;          // 0..15
    const int kbase = ks * 4;
    const int vbase = vg * 4;
    const bool b3   = (ks & 8) != 0;
    const bool b2   = (ks & 4) != 0;
    const int vidx  = vbase + (b3 ? 2 : 0) + (b2 ? 1 : 0);  // v stored by this lane
    const bool store_lane = (ks & 3) == 0;

    __shared__ float sq[2][CHUNK][Kdim];
    __shared__ float sk[2][CHUNK][Kdim];
    __shared__ float sw[2][CHUNK][Kdim];   // exp() applied in place per chunk
    __shared__ float sv[2][CHUNK][Vdim];
    __shared__ float squk[2][CHUNK];       // per-step  sum_k q*u*k
    __shared__ float su[Kdim];

    // state tile: s[v*2+p] holds S[kbase+2p .. kbase+2p+1][vbase+v]
    float2 s[8];
    {
        const size_t hb = (size_t)bh * Kdim * Vdim;
#pragma unroll
        for (int v = 0; v < 4; v++)
#pragma unroll
            for (int p = 0; p < 2; p++) {
                s[v * 2 + p].x = h0[hb + (size_t)(kbase + 2 * p)     * Vdim + vbase + v];
                s[v * 2 + p].y = h0[hb + (size_t)(kbase + 2 * p + 1) * Vdim + vbase + v];
            }
    }
    if (tid < Kdim) su[tid] = uin[h * Kdim + tid];

    const size_t base = (size_t)bh * Tdim * Kdim;   // also valid for v and o (K==V)

    const uint32_t sq_s = (uint32_t)__cvta_generic_to_shared(&sq[0][0][0]);
    const uint32_t sk_s = (uint32_t)__cvta_generic_to_shared(&sk[0][0][0]);
    const uint32_t sw_s = (uint32_t)__cvta_generic_to_shared(&sw[0][0][0]);
    const uint32_t sv_s = (uint32_t)__cvta_generic_to_shared(&sv[0][0][0]);

    // issue a chunk's 4 tensors as one cp.async group into buffer `buf`
    auto issue_chunk = [&](int c, int buf) {
        const size_t off = base + (size_t)c * CHUNK * Kdim;
        const uint32_t bofs = buf * CHUNK_BYTES + tid * 16;
        cp16(sq_s + bofs, r   + off + tid * 4);
        cp16(sk_s + bofs, kin + off + tid * 4);
        cp16(sw_s + bofs, win + off + tid * 4);
        cp16(sv_s + bofs, vin + off + tid * 4);
        asm volatile("cp.async.commit_group;");
    };

    issue_chunk(0, 0);
    issue_chunk(1, 1);

    for (int c = 0; c < NCHUNK; c++) {
        const int cur = c & 1;
        asm volatile("cp.async.wait_group 1;");
        __syncthreads();

        // ---- per-chunk preprocessing ----
        // exp(w) in place: 1024 values / 256 threads = one float4 each
        {
            float4* wf = (float4*)&sw[cur][0][0];
            float4 t = wf[tid];
            t.x = __expf(t.x); t.y = __expf(t.y);
            t.z = __expf(t.z); t.w = __expf(t.w);
            wf[tid] = t;
        }
        // quk[t] = sum_k q*u*k : 16 steps x 16 lanes, 4 k's each
        {
            const int stp  = tid >> 4;
            const int part = tid & 15;
            const float4 qq = *(const float4*)&sq[cur][stp][part * 4];
            const float4 kk = *(const float4*)&sk[cur][stp][part * 4];
            const float4 uu = *(const float4*)&su[part * 4];
            float sum = qq.x * kk.x * uu.x;
            sum = fmaf(qq.y * kk.y, uu.y, sum);
            sum = fmaf(qq.z * kk.z, uu.z, sum);
            sum = fmaf(qq.w * kk.w, uu.w, sum);
            sum += __shfl_xor_sync(0xffffffffu, sum, 1);
            sum += __shfl_xor_sync(0xffffffffu, sum, 2);
            sum += __shfl_xor_sync(0xffffffffu, sum, 4);
            sum += __shfl_xor_sync(0xffffffffu, sum, 8);
            if (part == 0) squk[cur][stp] = sum;
        }
        __syncthreads();

        // ---- compute 16 steps, no barriers ----
        const size_t obase = base + (size_t)c * CHUNK * Vdim;
#pragma unroll 4
        for (int tt = 0; tt < CHUNK; tt++) {
            const float4 q4 = *(const float4*)&sq[cur][tt][kbase];
            const float4 k4 = *(const float4*)&sk[cur][tt][kbase];
            const float4 e4 = *(const float4*)&sw[cur][tt][kbase];
            const float4 v4 = *(const float4*)&sv[cur][tt][vbase];

            const float2 q2a = make_float2(q4.x, q4.y);
            const float2 q2b = make_float2(q4.z, q4.w);
            const float2 k2a = make_float2(k4.x, k4.y);
            const float2 k2b = make_float2(k4.z, k4.w);
            const float2 e2a = make_float2(e4.x, e4.y);
            const float2 e2b = make_float2(e4.z, e4.w);
            const float vs[4] = {v4.x, v4.y, v4.z, v4.w};

            float a[4];
#pragma unroll
            for (int v = 0; v < 4; v++) {
                const float2 vv = make_float2(vs[v], vs[v]);
                const float2 kva = mul2(k2a, vv);
                const float2 kvb = mul2(k2b, vv);
                float2 acc = mul2(q2a, s[v * 2 + 0]);
                acc = fma2(q2b, s[v * 2 + 1], acc);
                s[v * 2 + 0] = fma2(s[v * 2 + 0], e2a, kva);
                s[v * 2 + 1] = fma2(s[v * 2 + 1], e2b, kvb);
                a[v] = acc.x + acc.y;
            }

            // value-distribution reduction over the 16 ks-lanes.
            // stage xor 8: keep (a0,a1) if b3==0 else (a2,a3)
            float sx = b3 ? a[0] : a[2];
            float sy = b3 ? a[1] : a[3];
            const float rx = __shfl_xor_sync(0xffffffffu, sx, 8);
            const float ry = __shfl_xor_sync(0xffffffffu, sy, 8);
            float p0 = (b3 ? a[2] : a[0]) + rx;
            float p1 = (b3 ? a[3] : a[1]) + ry;
            // stage xor 4: keep p0 if b2==0 else p1
            float snd = b2 ? p0 : p1;
            const float rz = __shfl_xor_sync(0xffffffffu, snd, 4);
            float red = (b2 ? p1 : p0) + rz;
            // stages xor 2, xor 1: plain butterfly
            red += __shfl_xor_sync(0xffffffffu, red, 2);
            red += __shfl_xor_sync(0xffffffffu, red, 1);

            if (store_lane) {
                const float vsel = b3 ? (b2 ? v4.w : v4.z) : (b2 ? v4.y : v4.x);
                o[obase + (size_t)tt * Vdim + vidx] = fmaf(squk[cur][tt], vsel, red);
            }
        }
        __syncthreads();   // all reads of `cur` done before refill

        if (c + 2 < NCHUNK)
            issue_chunk(c + 2, cur);
    }

    // final state: layout (B,H,K,V)
    {
        const size_t hb = (size_t)bh * Kdim * Vdim;
#pragma unroll
        for (int v = 0; v < 4; v++)
#pragma unroll
            for (int p = 0; p < 2; p++) {
                hT[hb + (size_t)(kbase + 2 * p)     * Vdim + vbase + v] = s[v * 2 + p].x;
                hT[hb + (size_t)(kbase + 2 * p + 1) * Vdim + vbase + v] = s[v * 2 + p].y;
            }
    }
}

extern "C" void kernel_launch(void* const* d_in, const int* in_sizes, int n_in,
                              void* d_out, int out_size) {
    const float* r  = (const float*)d_in[0];
    const float* k  = (const float*)d_in[1];
    const float* v  = (const float*)d_in[2];
    const float* w  = (const float*)d_in[3];
    const float* u  = (const float*)d_in[4];
    const float* h0 = (const float*)d_in[5];

    float* o  = (float*)d_out;
    float* hT = o + (size_t)Bdim * Hdim * Tdim * Vdim;

    rwkv6_scan_kernel<<<Bdim * Hdim, NTHREADS>>>(r, k, v, w, u, h0, o, hT);
}

// round 12
// speedup vs baseline: 3.5400x; 1.0077x over previous
#include <cuda_runtime.h>
#include <cstdint>

#define Bdim 4
#define Hdim 32
#define Tdim 2048
#define Kdim 64
#define Vdim 64
#define CHUNK 32
#define NCHUNK (Tdim / CHUNK)
#define NTHREADS 256
#define CHUNK_BYTES (CHUNK * Kdim * 4)   // 8192 B per tensor per chunk

// ---- packed f32x2 helpers (sm_103a FFMA2 path) ----
__device__ __forceinline__ float2 fma2(float2 a, float2 b, float2 c) {
    float2 d;
    asm("fma.rn.f32x2 %0, %1, %2, %3;"
        : "=l"(reinterpret_cast<unsigned long long&>(d))
        : "l"(reinterpret_cast<unsigned long long&>(a)),
          "l"(reinterpret_cast<unsigned long long&>(b)),
          "l"(reinterpret_cast<unsigned long long&>(c)));
    return d;
}
__device__ __forceinline__ float2 mul2(float2 a, float2 b) {
    float2 d;
    asm("mul.rn.f32x2 %0, %1, %2;"
        : "=l"(reinterpret_cast<unsigned long long&>(d))
        : "l"(reinterpret_cast<unsigned long long&>(a)),
          "l"(reinterpret_cast<unsigned long long&>(b)));
    return d;
}

__device__ __forceinline__ void cp16(uint32_t smem_dst, const void* gmem_src) {
    asm volatile("cp.async.cg.shared.global [%0], [%1], 16;"
                 :: "r"(smem_dst), "l"(gmem_src));
}

// Block = one (b,h). 256 threads: ks = tid&15 (K split 16x4), vg = tid>>4 (V split 16x4).
// Each thread owns a 4k x 4v state tile in registers (8 packed float2).
// Per step: o_v = sum_k q_k*S_kv + v_v*(sum_k q_k*u_k*k_k);  S = S*exp(w) + k*v.
// The 16-lane output reduction is split 2+2 stages and pipelined across steps.
__global__ __launch_bounds__(NTHREADS, 1)
void rwkv6_scan_kernel(const float* __restrict__ r,
                       const float* __restrict__ kin,
                       const float* __restrict__ vin,
                       const float* __restrict__ win,
                       const float* __restrict__ uin,
                       const float* __restrict__ h0,
                       float* __restrict__ o,
                       float* __restrict__ hT) {
    const int bh    = blockIdx.x;
    const int h     = bh % Hdim;
    const int tid   = threadIdx.x;
    const int ks    = tid & 15;
    const int vg    = tid >> 4;
    const int kbase = ks * 4;
    const int vbase = vg * 4;
    const bool b3   = (ks & 8) != 0;
    const bool b2   = (ks & 4) != 0;
    const int vidx  = vbase + (b3 ? 2 : 0) + (b2 ? 1 : 0);  // v stored by this lane
    const bool store_lane = (ks & 3) == 0;

    __shared__ float sq[2][CHUNK][Kdim];
    __shared__ float sk[2][CHUNK][Kdim];
    __shared__ float sw[2][CHUNK][Kdim];   // exp() applied in place per chunk
    __shared__ float sv[2][CHUNK][Vdim];
    __shared__ float squk[2][CHUNK];       // per-step  sum_k q*u*k
    __shared__ float su[Kdim];

    // state tile: s[v*2+p] holds S[kbase+2p .. kbase+2p+1][vbase+v]
    float2 s[8];
    {
        const size_t hb = (size_t)bh * Kdim * Vdim;
#pragma unroll
        for (int v = 0; v < 4; v++)
#pragma unroll
            for (int p = 0; p < 2; p++) {
                s[v * 2 + p].x = h0[hb + (size_t)(kbase + 2 * p)     * Vdim + vbase + v];
                s[v * 2 + p].y = h0[hb + (size_t)(kbase + 2 * p + 1) * Vdim + vbase + v];
            }
    }
    if (tid < Kdim) su[tid] = uin[h * Kdim + tid];

    const size_t base = (size_t)bh * Tdim * Kdim;   // also valid for v and o (K==V)

    const uint32_t sq_s = (uint32_t)__cvta_generic_to_shared(&sq[0][0][0]);
    const uint32_t sk_s = (uint32_t)__cvta_generic_to_shared(&sk[0][0][0]);
    const uint32_t sw_s = (uint32_t)__cvta_generic_to_shared(&sw[0][0][0]);
    const uint32_t sv_s = (uint32_t)__cvta_generic_to_shared(&sv[0][0][0]);

    // issue a chunk's 4 tensors as one cp.async group into buffer `buf`
    // 8192 B per tensor = 256 threads x 2 cp16
    auto issue_chunk = [&](int c, int buf) {
        const size_t off = base + (size_t)c * CHUNK * Kdim;
        const uint32_t bofs = buf * CHUNK_BYTES + tid * 16;
#pragma unroll
        for (int half = 0; half < 2; half++) {
            const uint32_t so = bofs + half * 4096;
            const size_t go = off + half * 1024 + tid * 4;
            cp16(sq_s + so, r   + go);
            cp16(sk_s + so, kin + go);
            cp16(sw_s + so, win + go);
            cp16(sv_s + so, vin + go);
        }
        asm volatile("cp.async.commit_group;");
    };

    issue_chunk(0, 0);
    issue_chunk(1, 1);

    for (int c = 0; c < NCHUNK; c++) {
        const int cur = c & 1;
        asm volatile("cp.async.wait_group 1;");
        __syncthreads();

        // ---- per-chunk preprocessing ----
        // exp(w) in place: 2048 values / 256 threads = two float4 each
        {
            float4* wf = (float4*)&sw[cur][0][0];
#pragma unroll
            for (int i = 0; i < 2; i++) {
                float4 t = wf[tid + i * NTHREADS];
                t.x = __expf(t.x); t.y = __expf(t.y);
                t.z = __expf(t.z); t.w = __expf(t.w);
                wf[tid + i * NTHREADS] = t;
            }
        }
        // quk[t] = sum_k q*u*k : 32 steps x 8 lanes, 8 k's each
        {
            const int stp  = tid >> 3;           // 0..31
            const int part = tid & 7;            // 0..7
            const float4* qq = (const float4*)&sq[cur][stp][part * 8];
            const float4* kk = (const float4*)&sk[cur][stp][part * 8];
            const float4* uu = (const float4*)&su[part * 8];
            float sum = 0.f;
#pragma unroll
            for (int i = 0; i < 2; i++) {
                const float4 q4 = qq[i], k4 = kk[i], u4 = uu[i];
                sum = fmaf(q4.x * k4.x, u4.x, sum);
                sum = fmaf(q4.y * k4.y, u4.y, sum);
                sum = fmaf(q4.z * k4.z, u4.z, sum);
                sum = fmaf(q4.w * k4.w, u4.w, sum);
            }
            sum += __shfl_xor_sync(0xffffffffu, sum, 1);
            sum += __shfl_xor_sync(0xffffffffu, sum, 2);
            sum += __shfl_xor_sync(0xffffffffu, sum, 4);
            if (part == 0) squk[cur][stp] = sum;
        }
        __syncthreads();

        // ---- compute CHUNK steps, no barriers; reduction pipelined 2+2 ----
        const size_t obase = base + (size_t)c * CHUNK * Vdim;
        float pend_red = 0.f;     // after stages xor8,xor4 of previous step
        float pend_bias = 0.f;    // squk[t-1] * v_sel[t-1]
#pragma unroll 4
        for (int tt = 0; tt < CHUNK; tt++) {
            const float4 q4 = *(const float4*)&sq[cur][tt][kbase];
            const float4 k4 = *(const float4*)&sk[cur][tt][kbase];
            const float4 e4 = *(const float4*)&sw[cur][tt][kbase];
            const float4 v4 = *(const float4*)&sv[cur][tt][vbase];

            const float2 q2a = make_float2(q4.x, q4.y);
            const float2 q2b = make_float2(q4.z, q4.w);
            const float2 k2a = make_float2(k4.x, k4.y);
            const float2 k2b = make_float2(k4.z, k4.w);
            const float2 e2a = make_float2(e4.x, e4.y);
            const float2 e2b = make_float2(e4.z, e4.w);
            const float vs[4] = {v4.x, v4.y, v4.z, v4.w};

            float a[4];
#pragma unroll
            for (int v = 0; v < 4; v++) {
                const float2 vv = make_float2(vs[v], vs[v]);
                const float2 kva = mul2(k2a, vv);
                const float2 kvb = mul2(k2b, vv);
                float2 acc = mul2(q2a, s[v * 2 + 0]);
                acc = fma2(q2b, s[v * 2 + 1], acc);
                s[v * 2 + 0] = fma2(s[v * 2 + 0], e2a, kva);
                s[v * 2 + 1] = fma2(s[v * 2 + 1], e2b, kvb);
                a[v] = acc.x + acc.y;
            }

            // finish previous step's reduction (data long ready -> cheap)
            if (tt > 0) {
                pend_red += __shfl_xor_sync(0xffffffffu, pend_red, 2);
                pend_red += __shfl_xor_sync(0xffffffffu, pend_red, 1);
                if (store_lane)
                    o[obase + (size_t)(tt - 1) * Vdim + vidx] = pend_red + pend_bias;
            }

            // stages xor8, xor4 for the current step (latency hidden by next iter)
            float sx = b3 ? a[0] : a[2];
            float sy = b3 ? a[1] : a[3];
            const float rx = __shfl_xor_sync(0xffffffffu, sx, 8);
            const float ry = __shfl_xor_sync(0xffffffffu, sy, 8);
            float p0 = (b3 ? a[2] : a[0]) + rx;
            float p1 = (b3 ? a[3] : a[1]) + ry;
            float snd = b2 ? p0 : p1;
            const float rz = __shfl_xor_sync(0xffffffffu, snd, 4);
            pend_red = (b2 ? p1 : p0) + rz;

            const float vsel = b3 ? (b2 ? v4.w : v4.z) : (b2 ? v4.y : v4.x);
            pend_bias = squk[cur][tt] * vsel;
        }
        // flush last step of the chunk
        pend_red += __shfl_xor_sync(0xffffffffu, pend_red, 2);
        pend_red += __shfl_xor_sync(0xffffffffu, pend_red, 1);
        if (store_lane)
            o[obase + (size_t)(CHUNK - 1) * Vdim + vidx] = pend_red + pend_bias;

        __syncthreads();   // all reads of `cur` done before refill

        if (c + 2 < NCHUNK)
            issue_chunk(c + 2, cur);
    }

    // final state: layout (B,H,K,V)
    {
        const size_t hb = (size_t)bh * Kdim * Vdim;
#pragma unroll
        for (int v = 0; v < 4; v++)
#pragma unroll
            for (int p = 0; p < 2; p++) {
                hT[hb + (size_t)(kbase + 2 * p)     * Vdim + vbase + v] = s[v * 2 + p].x;
                hT[hb + (size_t)(kbase + 2 * p + 1) * Vdim + vbase + v] = s[v * 2 + p].y;
            }
    }
}

extern "C" void kernel_launch(void* const* d_in, const int* in_sizes, int n_in,
                              void* d_out, int out_size) {
    const float* r  = (const float*)d_in[0];
    const float* k  = (const float*)d_in[1];
    const float* v  = (const float*)d_in[2];
    const float* w  = (const float*)d_in[3];
    const float* u  = (const float*)d_in[4];
    const float* h0 = (const float*)d_in[5];

    float* o  = (float*)d_out;
    float* hT = o + (size_t)Bdim * Hdim * Tdim * Vdim;

    rwkv6_scan_kernel<<<Bdim * Hdim, NTHREADS>>>(r, k, v, w, u, h0, o, hT);
}